// round 5
// baseline (speedup 1.0000x reference)
#include <cuda_runtime.h>
#include <math_constants.h>

#define BB 512
#define SS 200
#define UU 50
#define DD 32
#define NITER 13          // ceil(50 / 4 rows-per-iter) worst case (all unmasked)
#define NEG_INF_V (-1e9f)

__global__ __launch_bounds__(256)
void DIB_attn_kernel(const float* __restrict__ cur_user,   // [B, D]
                     const float* __restrict__ sim_user,   // [B, S, U, D]
                     const float* __restrict__ cur_item,   // [B, S, D]
                     const int* __restrict__ mask,          // [B, S, U] (bool -> int32)
                     float* __restrict__ out)               // [B, S, D]
{
    const unsigned FULL = 0xffffffffu;
    int gwarp = (blockIdx.x * blockDim.x + threadIdx.x) >> 5;   // one warp per (b,s)
    if (gwarp >= BB * SS) return;
    int lane = threadIdx.x & 31;
    int sub  = lane >> 3;       // 0..3 : compact-rank within 4-row group
    int quad = lane & 7;        // 0..7 : dims quad*4 .. quad*4+3

    int b = gwarp / SS;

    // ---- Mask first: build 50-bit "unmasked" bitmap (2 coalesced loads + ballots)
    const int* mrow = mask + (long long)gwarp * UU;
    int m0 = __ldg(mrow + lane);                        // u = lane (0..31)
    unsigned bits0 = __ballot_sync(FULL, m0 == 0);
    int u2 = 32 + lane;
    int m1 = (u2 < UU) ? __ldg(mrow + u2) : 1;          // u = 32..49
    unsigned bits1 = __ballot_sync(FULL, (u2 < UU) && (m1 == 0));

    int count = __popc(bits0) + __popc(bits1);
    bool degen = (count == 0);                          // all masked -> uniform softmax
    if (degen) { bits0 = 0xffffffffu; bits1 = 0x3ffffu; count = UU; }
    int c0 = __popc(bits0);

    float4 cu = __ldg((const float4*)(cur_user + b * DD) + quad);
    const float* tile = sim_user + (long long)gwarp * (UU * DD);

    // ---- Load ONLY unmasked rows (compacted), compute dot products ----
    float4 v[NITER];
    float  sc[NITER];

    #pragma unroll
    for (int i = 0; i < NITER; i++) {
        int r = i * 4 + sub;                            // compact rank
        bool valid = (r < count);
        float4 vv = make_float4(0.f, 0.f, 0.f, 0.f);
        if (valid) {
            int u = (r < c0) ? (int)__fns(bits0, 0, r + 1)
                             : 32 + (int)__fns(bits1, 0, r - c0 + 1);
            vv = __ldg((const float4*)(tile + u * DD) + quad);
        }
        v[i] = vv;

        float p = vv.x * cu.x + vv.y * cu.y + vv.z * cu.z + vv.w * cu.w;
        p += __shfl_xor_sync(FULL, p, 1);
        p += __shfl_xor_sync(FULL, p, 2);
        p += __shfl_xor_sync(FULL, p, 4);               // 8-lane group holds score

        // degen: all scores equal (0) -> uniform weights, matches reference exactly
        sc[i] = valid ? (degen ? 0.0f : p) : -CUDART_INF_F;
    }

    // ---- Softmax over compacted entries (masked rows have exactly-zero weight) ----
    float mx = sc[0];
    #pragma unroll
    for (int i = 1; i < NITER; i++) mx = fmaxf(mx, sc[i]);
    mx = fmaxf(mx, __shfl_xor_sync(FULL, mx, 8));
    mx = fmaxf(mx, __shfl_xor_sync(FULL, mx, 16));

    float e[NITER];
    float s = 0.f;
    #pragma unroll
    for (int i = 0; i < NITER; i++) { e[i] = __expf(sc[i] - mx); s += e[i]; }
    s += __shfl_xor_sync(FULL, s, 8);
    s += __shfl_xor_sync(FULL, s, 16);
    float inv = __frcp_rn(s);

    // ---- Weighted sum (weights lane-local; only loaded rows contribute) ----
    float4 o = make_float4(0.f, 0.f, 0.f, 0.f);
    #pragma unroll
    for (int i = 0; i < NITER; i++) {
        int r = i * 4 + sub;
        if (r < count) {
            float a = e[i] * inv;
            o.x = fmaf(a, v[i].x, o.x);
            o.y = fmaf(a, v[i].y, o.y);
            o.z = fmaf(a, v[i].z, o.z);
            o.w = fmaf(a, v[i].w, o.w);
        }
    }

    // Reduce partial outputs across the 4 sub groups (same dims, different rows).
    #pragma unroll
    for (int off = 8; off <= 16; off <<= 1) {
        o.x += __shfl_xor_sync(FULL, o.x, off);
        o.y += __shfl_xor_sync(FULL, o.y, off);
        o.z += __shfl_xor_sync(FULL, o.z, off);
        o.w += __shfl_xor_sync(FULL, o.w, off);
    }

    // sub==0 lanes (8 of them) write the 128B output row.
    if (sub == 0) {
        float4 ci = __ldg((const float4*)(cur_item + (long long)gwarp * DD) + quad);
        float4 r = make_float4(o.x + ci.x, o.y + ci.y, o.z + ci.z, o.w + ci.w);
        ((float4*)(out + (long long)gwarp * DD))[quad] = r;
    }
}

extern "C" void kernel_launch(void* const* d_in, const int* in_sizes, int n_in,
                              void* d_out, int out_size) {
    // Select inputs by element count (robust to ordering):
    const float* cur_user = nullptr;
    const float* sim_user = nullptr;
    const float* cur_item = nullptr;
    const int*   mask     = nullptr;
    for (int i = 0; i < n_in; i++) {
        switch (in_sizes[i]) {
            case 16384:     cur_user = (const float*)d_in[i]; break;
            case 163840000: sim_user = (const float*)d_in[i]; break;
            case 3276800:   cur_item = (const float*)d_in[i]; break;
            case 5120000:   mask     = (const int*)d_in[i];   break;
        }
    }
    float* out = (float*)d_out;

    int total_warps = BB * SS;              // 102400 (b,s) pairs, one warp each
    int threads = 256;
    int blocks = (total_warps * 32 + threads - 1) / threads;  // 12800
    DIB_attn_kernel<<<blocks, threads>>>(cur_user, sim_user, cur_item, mask, out);
}

// round 6
// speedup vs baseline: 1.8885x; 1.8885x over previous
#include <cuda_runtime.h>
#include <math_constants.h>

#define BB 512
#define SS 200
#define UU 50
#define DD 32
#define NITER 13          // ceil(50 rows / 4 rows-per-iter)
#define NEG_INF_V (-1e9f)

__global__ __launch_bounds__(256)
void DIB_attn_kernel(const float* __restrict__ cur_user,   // [B, D]
                     const float* __restrict__ sim_user,   // [B, S, U, D]
                     const float* __restrict__ cur_item,   // [B, S, D]
                     const int* __restrict__ mask,          // [B, S, U] (bool -> int32)
                     float* __restrict__ out)               // [B, S, D]
{
    const unsigned FULL = 0xffffffffu;
    int gwarp = (blockIdx.x * blockDim.x + threadIdx.x) >> 5;   // one warp per (b,s)
    if (gwarp >= BB * SS) return;
    int lane = threadIdx.x & 31;
    int sub  = lane >> 3;       // 0..3 : row within each 4-row group
    int quad = lane & 7;        // 0..7 : dims quad*4 .. quad*4+3

    int b = gwarp / SS;

    float4 cu = __ldg((const float4*)(cur_user + b * DD) + quad);
    const float* tile = sim_user + (long long)gwarp * (UU * DD);
    const int*   mrow = mask     + (long long)gwarp * UU;

    // Prefetch mask values for this lane's rows (coalesced 16B/iter per warp).
    int mreg[NITER];
    #pragma unroll
    for (int i = 0; i < NITER; i++) {
        int u = i * 4 + sub;
        mreg[i] = (u < UU) ? __ldg(mrow + u) : 1;
    }

    // Online softmax state per 8-lane row-group (rows {4i+sub}).
    float  m   = -CUDART_INF_F;
    float  s   = 0.0f;
    float4 acc = make_float4(0.f, 0.f, 0.f, 0.f);

    // Single streaming pass: one LDG.128 covers 4 rows (512B contiguous/warp).
    #pragma unroll
    for (int i = 0; i < NITER; i++) {
        int u = i * 4 + sub;
        bool valid = (u < UU);                       // only i==12, sub>=2 invalid
        float4 vv = make_float4(0.f, 0.f, 0.f, 0.f);
        if (valid) vv = __ldg((const float4*)(tile + u * DD) + quad);

        // dot over this lane's 4 dims, reduce across the 8 quads (doubles as bcast)
        float p = vv.x * cu.x + vv.y * cu.y + vv.z * cu.z + vv.w * cu.w;
        p += __shfl_xor_sync(FULL, p, 1);
        p += __shfl_xor_sync(FULL, p, 2);
        p += __shfl_xor_sync(FULL, p, 4);

        // masked -> -1e9 (finite, matches reference); pad rows -> -inf (weight 0)
        float sc = valid ? (mreg[i] ? NEG_INF_V : p) : -CUDART_INF_F;

        // online update. i==0 is always valid & finite, so mn is finite from the
        // start: factor=exp(-inf - finite)=0 at i==0, e=exp(-inf - mn)=0 for pads.
        float mn = fmaxf(m, sc);
        float factor = __expf(m - mn);
        float e      = __expf(sc - mn);
        s = s * factor + e;
        acc.x = acc.x * factor + e * vv.x;
        acc.y = acc.y * factor + e * vv.y;
        acc.z = acc.z * factor + e * vv.z;
        acc.w = acc.w * factor + e * vv.w;
        m = mn;
    }

    // Combine the 4 sub-group softmax states (union of their rows = all 50).
    float M = m;
    M = fmaxf(M, __shfl_xor_sync(FULL, M, 8));
    M = fmaxf(M, __shfl_xor_sync(FULL, M, 16));

    float corr = __expf(m - M);          // m finite for every sub-group (i==0 valid)
    float st = s * corr;
    st += __shfl_xor_sync(FULL, st, 8);
    st += __shfl_xor_sync(FULL, st, 16);

    float w = corr * __frcp_rn(st);      // st>0 always (all-masked -> st = 50)
    float4 o = make_float4(acc.x * w, acc.y * w, acc.z * w, acc.w * w);

    // Reduce partial outputs across the 4 sub groups (same dims, different rows).
    #pragma unroll
    for (int off = 8; off <= 16; off <<= 1) {
        o.x += __shfl_xor_sync(FULL, o.x, off);
        o.y += __shfl_xor_sync(FULL, o.y, off);
        o.z += __shfl_xor_sync(FULL, o.z, off);
        o.w += __shfl_xor_sync(FULL, o.w, off);
    }

    // sub==0 lanes (8 of them) write the 128B output row.
    if (sub == 0) {
        float4 ci = __ldg((const float4*)(cur_item + (long long)gwarp * DD) + quad);
        float4 r = make_float4(o.x + ci.x, o.y + ci.y, o.z + ci.z, o.w + ci.w);
        ((float4*)(out + (long long)gwarp * DD))[quad] = r;
    }
}

extern "C" void kernel_launch(void* const* d_in, const int* in_sizes, int n_in,
                              void* d_out, int out_size) {
    // Select inputs by element count (robust to ordering):
    const float* cur_user = nullptr;
    const float* sim_user = nullptr;
    const float* cur_item = nullptr;
    const int*   mask     = nullptr;
    for (int i = 0; i < n_in; i++) {
        switch (in_sizes[i]) {
            case 16384:     cur_user = (const float*)d_in[i]; break;
            case 163840000: sim_user = (const float*)d_in[i]; break;
            case 3276800:   cur_item = (const float*)d_in[i]; break;
            case 5120000:   mask     = (const int*)d_in[i];   break;
        }
    }
    float* out = (float*)d_out;

    int total_warps = BB * SS;              // 102400 (b,s) pairs, one warp each
    int threads = 256;
    int blocks = (total_warps * 32 + threads - 1) / threads;  // 12800
    DIB_attn_kernel<<<blocks, threads>>>(cur_user, sim_user, cur_item, mask, out);
}

// round 7
// speedup vs baseline: 2.4378x; 1.2909x over previous
#include <cuda_runtime.h>
#include <math_constants.h>

#define BB 512
#define SS 200
#define UU 50
#define DD 32
#define NITER 13          // ceil(50 rows / 4 rows-per-iter)
#define NEG_INF_V (-1e9f)

__global__ __launch_bounds__(256)
void DIB_attn_kernel(const float* __restrict__ cur_user,   // [B, D]
                     const float* __restrict__ sim_user,   // [B, S, U, D]
                     const float* __restrict__ cur_item,   // [B, S, D]
                     const int* __restrict__ mask,          // [B, S, U] (bool -> int32)
                     float* __restrict__ out)               // [B, S, D]
{
    const unsigned FULL = 0xffffffffu;
    int gwarp = (blockIdx.x * blockDim.x + threadIdx.x) >> 5;   // one warp per (b,s)
    if (gwarp >= BB * SS) return;
    int lane = threadIdx.x & 31;
    int sub  = lane >> 3;       // 0..3 : row within 4-row group
    int quad = lane & 7;        // 0..7 : dims quad*4 .. quad*4+3

    int b = gwarp / SS;

    // ---- Mask first: 2 coalesced loads + 2 ballots -> 50-bit "unmasked" bitmap.
    const int* mrow = mask + (long long)gwarp * UU;
    int m0 = __ldg(mrow + lane);                        // u = 0..31
    unsigned bits0 = __ballot_sync(FULL, m0 == 0);
    int u2 = 32 + lane;
    int m1 = (u2 < UU) ? __ldg(mrow + u2) : 1;          // u = 32..49
    unsigned bits1 = __ballot_sync(FULL, (u2 < UU) && (m1 == 0));
    bool degen = (bits0 | bits1) == 0u;                 // all masked -> uniform

    float4 cu = __ldg((const float4*)(cur_user + b * DD) + quad);
    const float* tile = sim_user + (long long)gwarp * (UU * DD);

    // ---- Predicated tile load: masked rows make NO memory request (their
    //      128B line = 4 sectors is never fetched). Addresses identical to the
    //      full stream; no compaction, no gather.
    float4 v[NITER];
    #pragma unroll
    for (int i = 0; i < NITER; i++) {
        int u = i * 4 + sub;
        bool inb = (u < UU);
        bool un  = inb && (((u < 32 ? (bits0 >> u) : (bits1 >> (u - 32))) & 1u) != 0u);
        float4 vv = make_float4(0.f, 0.f, 0.f, 0.f);
        if (inb && (un || degen))
            vv = __ldg((const float4*)(tile + u * DD) + quad);
        v[i] = vv;
    }

    // ---- Dot products + scores (masked -> -1e9, pad -> -inf) ----
    float sc[NITER];
    #pragma unroll
    for (int i = 0; i < NITER; i++) {
        int u = i * 4 + sub;
        float p = v[i].x * cu.x + v[i].y * cu.y + v[i].z * cu.z + v[i].w * cu.w;
        p += __shfl_xor_sync(FULL, p, 1);
        p += __shfl_xor_sync(FULL, p, 2);
        p += __shfl_xor_sync(FULL, p, 4);               // 8-lane group holds score[u]
        bool inb = (u < UU);
        bool un  = inb && (((u < 32 ? (bits0 >> u) : (bits1 >> (u - 32))) & 1u) != 0u);
        sc[i] = inb ? (un ? p : NEG_INF_V) : -CUDART_INF_F;
    }

    // ---- Softmax over all 50 (masked rows get weight exactly 0; degen case:
    //      all sc=-1e9 -> uniform 1/50 over fully-loaded tile, matching ref) ----
    float mx = sc[0];
    #pragma unroll
    for (int i = 1; i < NITER; i++) mx = fmaxf(mx, sc[i]);
    mx = fmaxf(mx, __shfl_xor_sync(FULL, mx, 8));
    mx = fmaxf(mx, __shfl_xor_sync(FULL, mx, 16));

    float e[NITER];
    float s = 0.f;
    #pragma unroll
    for (int i = 0; i < NITER; i++) { e[i] = __expf(sc[i] - mx); s += e[i]; }
    s += __shfl_xor_sync(FULL, s, 8);
    s += __shfl_xor_sync(FULL, s, 16);
    float inv = __frcp_rn(s);

    // ---- Weighted sum (weights lane-local; v=0 for skipped rows anyway) ----
    float4 o = make_float4(0.f, 0.f, 0.f, 0.f);
    #pragma unroll
    for (int i = 0; i < NITER; i++) {
        float a = e[i] * inv;
        o.x = fmaf(a, v[i].x, o.x);
        o.y = fmaf(a, v[i].y, o.y);
        o.z = fmaf(a, v[i].z, o.z);
        o.w = fmaf(a, v[i].w, o.w);
    }

    // Reduce partial outputs across the 4 sub groups (same dims, different rows).
    #pragma unroll
    for (int off = 8; off <= 16; off <<= 1) {
        o.x += __shfl_xor_sync(FULL, o.x, off);
        o.y += __shfl_xor_sync(FULL, o.y, off);
        o.z += __shfl_xor_sync(FULL, o.z, off);
        o.w += __shfl_xor_sync(FULL, o.w, off);
    }

    // sub==0 lanes (8 of them) write the 128B output row.
    if (sub == 0) {
        float4 ci = __ldg((const float4*)(cur_item + (long long)gwarp * DD) + quad);
        float4 r = make_float4(o.x + ci.x, o.y + ci.y, o.z + ci.z, o.w + ci.w);
        ((float4*)(out + (long long)gwarp * DD))[quad] = r;
    }
}

extern "C" void kernel_launch(void* const* d_in, const int* in_sizes, int n_in,
                              void* d_out, int out_size) {
    // Select inputs by element count (robust to ordering):
    const float* cur_user = nullptr;
    const float* sim_user = nullptr;
    const float* cur_item = nullptr;
    const int*   mask     = nullptr;
    for (int i = 0; i < n_in; i++) {
        switch (in_sizes[i]) {
            case 16384:     cur_user = (const float*)d_in[i]; break;
            case 163840000: sim_user = (const float*)d_in[i]; break;
            case 3276800:   cur_item = (const float*)d_in[i]; break;
            case 5120000:   mask     = (const int*)d_in[i];   break;
        }
    }
    float* out = (float*)d_out;

    int total_warps = BB * SS;              // 102400 (b,s) pairs, one warp each
    int threads = 256;
    int blocks = (total_warps * 32 + threads - 1) / threads;  // 12800
    DIB_attn_kernel<<<blocks, threads>>>(cur_user, sim_user, cur_item, mask, out);
}